// round 1
// baseline (speedup 1.0000x reference)
#include <cuda_runtime.h>
#include <math.h>

#define SLEN 1024
#define DDIM 2048
#define ENUM 8
#define HNUM 6
#define DKC  256
#define DVC  512
#define KDIM 1536   // HNUM*DKC
#define VDIM 3072   // HNUM*DVC
#define CAP  1024
#define NROW (ENUM*CAP)

// ---------------- scratch (device globals; no allocation in kernel_launch) ----
__device__ int   d_sel[SLEN*2];
__device__ float d_rw [SLEN*2];
__device__ int   d_m  [ENUM];
__device__ int   d_tok[NROW];
__device__ int   d_pos[SLEN*2];
__device__ float d_xg  [NROW*DDIM];
__device__ float d_qpre[NROW*KDIM];
__device__ float d_kpre[NROW*KDIM];
__device__ float d_vpre[NROW*VDIM];
__device__ float d_qn  [NROW*KDIM];
__device__ float d_kn  [NROW*KDIM];
__device__ float d_vn  [NROW*VDIM];
__device__ float d_beta[NROW*HNUM];
__device__ float d_g   [NROW*HNUM];
__device__ float d_o   [NROW*VDIM];
__device__ float d_gg  [SLEN*VDIM];
__device__ float d_pre [SLEN*VDIM];

// ---------------- router: logits -> softmax -> top2 -> renorm ---------------
__global__ void router_kernel(const float* __restrict__ hidden,
                              const float* __restrict__ gate_w) {
    int s = blockIdx.x;
    int tid = threadIdx.x;
    float acc[ENUM];
#pragma unroll
    for (int e = 0; e < ENUM; e++) acc[e] = 0.f;
    const float* xr = hidden + (size_t)s * DDIM;
    for (int d = tid; d < DDIM; d += 256) {
        float x = xr[d];
        const float* w = gate_w + (size_t)d * ENUM;
#pragma unroll
        for (int e = 0; e < ENUM; e++) acc[e] += x * w[e];
    }
    __shared__ float red[ENUM][256];
#pragma unroll
    for (int e = 0; e < ENUM; e++) red[e][tid] = acc[e];
    __syncthreads();
    for (int st = 128; st > 0; st >>= 1) {
        if (tid < st) {
#pragma unroll
            for (int e = 0; e < ENUM; e++) red[e][tid] += red[e][tid + st];
        }
        __syncthreads();
    }
    if (tid == 0) {
        float l[ENUM], mx = -1e30f;
#pragma unroll
        for (int e = 0; e < ENUM; e++) { l[e] = red[e][0]; mx = fmaxf(mx, l[e]); }
        float p[ENUM], sum = 0.f;
#pragma unroll
        for (int e = 0; e < ENUM; e++) { p[e] = expf(l[e] - mx); sum += p[e]; }
#pragma unroll
        for (int e = 0; e < ENUM; e++) p[e] /= sum;
        int i0 = 0;
#pragma unroll
        for (int e = 1; e < ENUM; e++) if (p[e] > p[i0]) i0 = e;
        int i1 = -1;
#pragma unroll
        for (int e = 0; e < ENUM; e++)
            if (e != i0 && (i1 < 0 || p[e] > p[i1])) i1 = e;
        float r0 = p[i0], r1 = p[i1], rs = r0 + r1;
        d_sel[2 * s] = i0;  d_sel[2 * s + 1] = i1;
        d_rw[2 * s] = r0 / rs;  d_rw[2 * s + 1] = r1 / rs;
    }
}

// -------------- dispatch: per-expert ranks, drops, compact mapping ----------
__global__ void dispatch_kernel() {
    int e = threadIdx.x;
    if (e >= ENUM) return;
    int c = 0;
    for (int i = 0; i < SLEN * 2; i++) c += (d_sel[i] == e);
    int drop = c > CAP ? c - CAP : 0;
    d_m[e] = c - drop;
    int r = 0;
    for (int i = 0; i < SLEN * 2; i++) {
        if (d_sel[i] == e) {
            if (r >= drop) {
                int j = r - drop;
                d_tok[e * CAP + j] = i >> 1;
                d_pos[i] = e * CAP + j;
            } else {
                d_pos[i] = -1;
            }
            r++;
        }
    }
}

// -------------- gather valid tokens into compact per-expert buffers ---------
__global__ void gather_kernel(const float* __restrict__ hidden) {
    int row = blockIdx.x;
    int e = row >> 10, t = row & 1023;
    if (t >= d_m[e]) return;
    const float* src = hidden + (size_t)d_tok[row] * DDIM;
    float* dst = d_xg + (size_t)row * DDIM;
    for (int d = threadIdx.x * 4; d < DDIM; d += 256 * 4)
        *(float4*)(dst + d) = *(const float4*)(src + d);
}

// -------------- generic fp32 tiled GEMM: C = A @ W, optional per-expert M ---
__global__ void gemm64(const float* __restrict__ A, const float* __restrict__ W,
                       float* __restrict__ C, int M, int N, int K,
                       long long aStride, long long wStride, long long cStride,
                       int useM) {
    int z = blockIdx.z;
    int mlim = useM ? d_m[z] : M;
    int row0 = blockIdx.y * 64;
    if (row0 >= mlim) return;
    A += (size_t)z * aStride; W += (size_t)z * wStride; C += (size_t)z * cStride;
    int col0 = blockIdx.x * 64;
    __shared__ float As[16][68];
    __shared__ float Bs[16][64];
    int tid = threadIdx.x;
    int tm = tid >> 4, tn = tid & 15;
    float acc[4][4];
#pragma unroll
    for (int i = 0; i < 4; i++)
#pragma unroll
        for (int j = 0; j < 4; j++) acc[i][j] = 0.f;

    int arow = row0 + (tid >> 2);
    int ak = (tid & 3) * 4;
    int am = tid >> 2;
    int brow = tid >> 4;
    int bcol4 = (tid & 15) * 4;
    const float* Aptr = A + (size_t)arow * K + ak;
    const float* Wptr = W + (size_t)brow * N + col0 + bcol4;
    bool aval = arow < mlim;

    for (int k0 = 0; k0 < K; k0 += 16) {
        float4 av = aval ? *(const float4*)(Aptr + k0) : make_float4(0, 0, 0, 0);
        As[ak + 0][am] = av.x; As[ak + 1][am] = av.y;
        As[ak + 2][am] = av.z; As[ak + 3][am] = av.w;
        *(float4*)&Bs[brow][bcol4] = *(const float4*)(Wptr + (size_t)k0 * N);
        __syncthreads();
#pragma unroll
        for (int kk = 0; kk < 16; kk++) {
            float4 a = *(const float4*)&As[kk][tm * 4];
            float4 b = *(const float4*)&Bs[kk][tn * 4];
            acc[0][0] += a.x * b.x; acc[0][1] += a.x * b.y; acc[0][2] += a.x * b.z; acc[0][3] += a.x * b.w;
            acc[1][0] += a.y * b.x; acc[1][1] += a.y * b.y; acc[1][2] += a.y * b.z; acc[1][3] += a.y * b.w;
            acc[2][0] += a.z * b.x; acc[2][1] += a.z * b.y; acc[2][2] += a.z * b.z; acc[2][3] += a.z * b.w;
            acc[3][0] += a.w * b.x; acc[3][1] += a.w * b.y; acc[3][2] += a.w * b.z; acc[3][3] += a.w * b.w;
        }
        __syncthreads();
    }
#pragma unroll
    for (int i = 0; i < 4; i++) {
        int r = row0 + tm * 4 + i;
        float4 val = make_float4(acc[i][0], acc[i][1], acc[i][2], acc[i][3]);
        *(float4*)(C + (size_t)r * N + col0 + tn * 4) = val;
    }
}

// -------------- beta / g projections (N=6 each): warp per row ----------------
__global__ void bg_kernel(const float* __restrict__ b_w, const float* __restrict__ a_w,
                          const float* __restrict__ A_log, const float* __restrict__ dt_bias) {
    int row = blockIdx.x * 8 + (threadIdx.x >> 5);
    int lane = threadIdx.x & 31;
    int e = row >> 10, t = row & 1023;
    if (t >= d_m[e]) return;
    const float* x = d_xg + (size_t)row * DDIM;
    const float* bw = b_w + (size_t)e * DDIM * HNUM;
    const float* aw = a_w + (size_t)e * DDIM * HNUM;
    float ba[HNUM], aa[HNUM];
#pragma unroll
    for (int h = 0; h < HNUM; h++) { ba[h] = 0.f; aa[h] = 0.f; }
    for (int d = lane; d < DDIM; d += 32) {
        float xv = x[d];
        const float* bp = bw + (size_t)d * HNUM;
        const float* ap = aw + (size_t)d * HNUM;
#pragma unroll
        for (int h = 0; h < HNUM; h++) { ba[h] += xv * bp[h]; aa[h] += xv * ap[h]; }
    }
#pragma unroll
    for (int h = 0; h < HNUM; h++) {
#pragma unroll
        for (int o = 16; o; o >>= 1) {
            ba[h] += __shfl_xor_sync(0xffffffffu, ba[h], o);
            aa[h] += __shfl_xor_sync(0xffffffffu, aa[h], o);
        }
    }
    if (lane == 0) {
#pragma unroll
        for (int h = 0; h < HNUM; h++) {
            d_beta[row * HNUM + h] = 1.f / (1.f + expf(-ba[h]));
            float xx = aa[h] + dt_bias[h];
            float sp = xx > 20.f ? xx : log1pf(expf(xx));
            d_g[row * HNUM + h] = -expf(A_log[h]) * sp;
        }
    }
}

// -------------- depthwise causal conv(4) + silu + per-head l2norm (q,k) -----
__global__ void convnorm_kernel(const float* __restrict__ pre, const float* __restrict__ cw,
                                float* __restrict__ out, float scale) {
    int row = blockIdx.x;
    int h = blockIdx.y;
    int e = row >> 10, t = row & 1023;
    if (t >= d_m[e]) return;
    int tid = threadIdx.x;
    int ch = h * DKC + tid;
    float y = 0.f;
#pragma unroll
    for (int j = 0; j < 4; j++) {
        int tt = t - 3 + j;
        if (tt >= 0) y += cw[ch * 4 + j] * pre[(size_t)(row - 3 + j) * KDIM + ch];
    }
    y = y / (1.f + expf(-y));      // silu
    __shared__ float red[256];
    red[tid] = y * y;
    __syncthreads();
    for (int st = 128; st > 0; st >>= 1) {
        if (tid < st) red[tid] += red[tid + st];
        __syncthreads();
    }
    float inv = rsqrtf(red[0] + 1e-6f) * scale;
    out[(size_t)row * KDIM + ch] = y * inv;
}

// -------------- depthwise causal conv(4) + silu for v ------------------------
__global__ void convv_kernel(const float* __restrict__ pre, const float* __restrict__ cw,
                             float* __restrict__ out) {
    int idx = blockIdx.x * 256 + threadIdx.x;
    int row = idx / VDIM;
    int ch = idx - row * VDIM;
    int e = row >> 10, t = row & 1023;
    if (t >= d_m[e]) return;
    float y = 0.f;
#pragma unroll
    for (int j = 0; j < 4; j++) {
        int tt = t - 3 + j;
        if (tt >= 0) y += cw[ch * 4 + j] * pre[(size_t)(row - 3 + j) * VDIM + ch];
    }
    out[(size_t)row * VDIM + ch] = y / (1.f + expf(-y));
}

// -------------- gated delta-rule recurrence ----------------------------------
// block = (e, h, vchunk of 32). State S[32][256] in smem. Warp-private 4 v-lanes.
// carries u = k_t . S_{t-1}, w = q_t . S_{t-1} computed in previous fused pass.
__global__ void recur_kernel() {
    int vc = blockIdx.x;           // 0..15
    int h = blockIdx.y;            // 0..5
    int e = blockIdx.z;            // 0..7
    int m = d_m[e];
    __shared__ float S[32 * 256];
    __shared__ float su[32], sw[32], sd[32];
    int tid = threadIdx.x, warp = tid >> 5, lane = tid & 31;
    int v0 = warp * 4;
    for (int i = lane; i < 4 * 256; i += 32) S[v0 * 256 + i] = 0.f;
    if (lane < 4) { su[v0 + lane] = 0.f; sw[v0 + lane] = 0.f; }
    __syncwarp();
    if (m == 0) return;

    const float* kb = d_kn + (size_t)(e * CAP) * KDIM + h * DKC;
    const float* qb = d_qn + (size_t)(e * CAP) * KDIM + h * DKC;
    const float* vb = d_vn + (size_t)(e * CAP) * VDIM + h * DVC + vc * 32;
    const float* bb = d_beta + (size_t)(e * CAP) * HNUM + h;
    const float* gb = d_g + (size_t)(e * CAP) * HNUM + h;
    float* ob = d_o + (size_t)(e * CAP) * VDIM + h * DVC + vc * 32;

    float kc[8], qc[8];
#pragma unroll
    for (int j = 0; j < 8; j++) { kc[j] = kb[lane + 32 * j]; qc[j] = qb[lane + 32 * j]; }

    for (int t = 0; t < m; t++) {
        float beta = bb[(size_t)t * HNUM];
        float gv = gb[(size_t)t * HNUM];
        float eg = expf(gv);
        float qk = 0.f;
#pragma unroll
        for (int j = 0; j < 8; j++) qk += kc[j] * qc[j];
#pragma unroll
        for (int o = 16; o; o >>= 1) qk += __shfl_xor_sync(0xffffffffu, qk, o);

        if (lane < 4) {
            int v = v0 + lane;
            float vv = vb[(size_t)t * VDIM + v];
            float dd = beta * (vv - eg * su[v]);
            ob[(size_t)t * VDIM + v] = eg * sw[v] + qk * dd;
            sd[v] = dd;
        }
        __syncwarp();

        float kn2[8], qn2[8];
        if (t + 1 < m) {
            const float* kr = kb + (size_t)(t + 1) * KDIM;
            const float* qr = qb + (size_t)(t + 1) * KDIM;
#pragma unroll
            for (int j = 0; j < 8; j++) { kn2[j] = kr[lane + 32 * j]; qn2[j] = qr[lane + 32 * j]; }
        } else {
#pragma unroll
            for (int j = 0; j < 8; j++) { kn2[j] = 0.f; qn2[j] = 0.f; }
        }

#pragma unroll
        for (int vi = 0; vi < 4; vi++) {
            int v = v0 + vi;
            float dd = sd[v];
            float un = 0.f, wn = 0.f;
            float* Sr = &S[v * 256];
#pragma unroll
            for (int j = 0; j < 8; j++) {
                float s2 = Sr[lane + 32 * j];
                s2 = eg * s2 + kc[j] * dd;
                Sr[lane + 32 * j] = s2;
                un += kn2[j] * s2;
                wn += qn2[j] * s2;
            }
#pragma unroll
            for (int o = 16; o; o >>= 1) {
                un += __shfl_xor_sync(0xffffffffu, un, o);
                wn += __shfl_xor_sync(0xffffffffu, wn, o);
            }
            if (lane == 0) { su[v] = un; sw[v] = wn; }
        }
        __syncwarp();
#pragma unroll
        for (int j = 0; j < 8; j++) { kc[j] = kn2[j]; qc[j] = qn2[j]; }
    }
}

// -------------- combine (scatter back) + gated RMSNorm -----------------------
__global__ void combine_kernel(const float* __restrict__ norm_w) {
    int s = blockIdx.x, h = blockIdx.y, tid = threadIdx.x;
    int p0 = d_pos[2 * s], p1 = d_pos[2 * s + 1];
    float r0 = d_rw[2 * s], r1 = d_rw[2 * s + 1];
    float acc[2];
    float ss = 0.f;
#pragma unroll
    for (int i = 0; i < 2; i++) {
        int v = tid + i * 256;
        float a = 0.f;
        if (p0 >= 0) a += r0 * d_o[(size_t)p0 * VDIM + h * DVC + v];
        if (p1 >= 0) a += r1 * d_o[(size_t)p1 * VDIM + h * DVC + v];
        acc[i] = a;
        ss += a * a;
    }
    __shared__ float red[256];
    red[tid] = ss;
    __syncthreads();
    for (int st = 128; st > 0; st >>= 1) {
        if (tid < st) red[tid] += red[tid + st];
        __syncthreads();
    }
    float inv = rsqrtf(red[0] / (float)DVC + 1e-5f);
#pragma unroll
    for (int i = 0; i < 2; i++) {
        int v = tid + i * 256;
        float gg = d_gg[(size_t)s * VDIM + h * DVC + v];
        float sg = gg / (1.f + expf(-gg));
        d_pre[(size_t)s * VDIM + h * DVC + v] = acc[i] * inv * norm_w[v] * sg;
    }
}

// ----------------------------- launch ----------------------------------------
extern "C" void kernel_launch(void* const* d_in, const int* in_sizes, int n_in,
                              void* d_out, int out_size) {
    const float* hidden  = (const float*)d_in[0];
    const float* q_w     = (const float*)d_in[1];
    const float* gate_w  = (const float*)d_in[2];
    const float* k_w     = (const float*)d_in[3];
    const float* v_w     = (const float*)d_in[4];
    const float* b_w     = (const float*)d_in[5];
    const float* a_w     = (const float*)d_in[6];
    const float* A_log   = (const float*)d_in[7];
    const float* dt_bias = (const float*)d_in[8];
    const float* qcw     = (const float*)d_in[9];
    const float* kcw     = (const float*)d_in[10];
    const float* vcw     = (const float*)d_in[11];
    const float* g_w     = (const float*)d_in[12];
    const float* norm_w  = (const float*)d_in[13];
    const float* o_w     = (const float*)d_in[14];

    float *xg, *qpre, *kpre, *vpre, *gg, *pre;
    cudaGetSymbolAddress((void**)&xg, d_xg);
    cudaGetSymbolAddress((void**)&qpre, d_qpre);
    cudaGetSymbolAddress((void**)&kpre, d_kpre);
    cudaGetSymbolAddress((void**)&vpre, d_vpre);
    cudaGetSymbolAddress((void**)&gg, d_gg);
    cudaGetSymbolAddress((void**)&pre, d_pre);

    router_kernel<<<SLEN, 256>>>(hidden, gate_w);
    dispatch_kernel<<<1, 32>>>();
    gather_kernel<<<NROW, 256>>>(hidden);

    dim3 gq(KDIM / 64, CAP / 64, ENUM);
    gemm64<<<gq, 256>>>(xg, q_w, qpre, CAP, KDIM, DDIM,
                        (long long)CAP * DDIM, 0LL, (long long)CAP * KDIM, 1);
    gemm64<<<gq, 256>>>(xg, k_w, kpre, CAP, KDIM, DDIM,
                        (long long)CAP * DDIM, (long long)DDIM * KDIM,
                        (long long)CAP * KDIM, 1);
    dim3 gv(VDIM / 64, CAP / 64, ENUM);
    gemm64<<<gv, 256>>>(xg, v_w, vpre, CAP, VDIM, DDIM,
                        (long long)CAP * DDIM, (long long)DDIM * VDIM,
                        (long long)CAP * VDIM, 1);

    bg_kernel<<<NROW / 8, 256>>>(b_w, a_w, A_log, dt_bias);

    float *qn, *kn, *vn;
    cudaGetSymbolAddress((void**)&qn, d_qn);
    cudaGetSymbolAddress((void**)&kn, d_kn);
    cudaGetSymbolAddress((void**)&vn, d_vn);

    dim3 gc(NROW, HNUM);
    convnorm_kernel<<<gc, 256>>>(qpre, qcw, qn, 0.0625f);  // DK^-0.5 = 1/16
    convnorm_kernel<<<gc, 256>>>(kpre, kcw, kn, 1.0f);
    convv_kernel<<<(NROW * (VDIM / 256)), 256>>>(vpre, vcw, vn);

    recur_kernel<<<dim3(DVC / 32, HNUM, ENUM), 256>>>();

    gemm64<<<dim3(VDIM / 64, SLEN / 64, 1), 256>>>(hidden, g_w, gg, SLEN, VDIM, DDIM,
                                                   0LL, 0LL, 0LL, 0);
    combine_kernel<<<dim3(SLEN, HNUM), 256>>>(norm_w);
    gemm64<<<dim3(DDIM / 64, SLEN / 64, 1), 256>>>(pre, o_w, (float*)d_out,
                                                   SLEN, DDIM, VDIM, 0LL, 0LL, 0LL, 0);
}

// round 2
// speedup vs baseline: 1.0033x; 1.0033x over previous
#include <cuda_runtime.h>
#include <math.h>

#define SLEN 1024
#define DDIM 2048
#define ENUM 8
#define HNUM 6
#define DKC  256
#define DVC  512
#define KDIM 1536   // HNUM*DKC
#define VDIM 3072   // HNUM*DVC
#define CAP  1024
#define NROW (ENUM*CAP)

// ---------------- scratch (device globals; no allocation in kernel_launch) ----
__device__ int   d_sel[SLEN*2];
__device__ float d_rw [SLEN*2];
__device__ int   d_m  [ENUM];
__device__ int   d_tok[NROW];
__device__ int   d_pos[SLEN*2];
__device__ float d_xg  [NROW*DDIM];
__device__ float d_qpre[NROW*KDIM];
__device__ float d_kpre[NROW*KDIM];
__device__ float d_vpre[NROW*VDIM];
__device__ float d_qn  [NROW*KDIM];
__device__ float d_kn  [NROW*KDIM];
__device__ float d_vn  [NROW*VDIM];
__device__ float d_beta[NROW*HNUM];
__device__ float d_g   [NROW*HNUM];
__device__ float d_o   [NROW*VDIM];
__device__ float d_gg  [SLEN*VDIM];
__device__ float d_pre [SLEN*VDIM];

// ---------------- f32x2 packed-FMA helpers (B300 FFMA2, PTX-only) ------------
__device__ __forceinline__ unsigned long long pk2(float x, float y) {
    unsigned long long r;
    asm("mov.b64 %0, {%1, %2};" : "=l"(r) : "f"(x), "f"(y));
    return r;
}
__device__ __forceinline__ unsigned long long fma2(unsigned long long a,
                                                   unsigned long long b,
                                                   unsigned long long c) {
    unsigned long long d;
    asm("fma.rn.f32x2 %0, %1, %2, %3;" : "=l"(d) : "l"(a), "l"(b), "l"(c));
    return d;
}
__device__ __forceinline__ float2 upk2(unsigned long long u) {
    float2 f;
    asm("mov.b64 {%0, %1}, %2;" : "=f"(f.x), "=f"(f.y) : "l"(u));
    return f;
}

// ---------------- router: logits -> softmax -> top2 -> renorm ---------------
__global__ void router_kernel(const float* __restrict__ hidden,
                              const float* __restrict__ gate_w) {
    int s = blockIdx.x;
    int tid = threadIdx.x;
    float acc[ENUM];
#pragma unroll
    for (int e = 0; e < ENUM; e++) acc[e] = 0.f;
    const float* xr = hidden + (size_t)s * DDIM;
    for (int d = tid; d < DDIM; d += 256) {
        float x = xr[d];
        const float* w = gate_w + (size_t)d * ENUM;
#pragma unroll
        for (int e = 0; e < ENUM; e++) acc[e] += x * w[e];
    }
    __shared__ float red[ENUM][256];
#pragma unroll
    for (int e = 0; e < ENUM; e++) red[e][tid] = acc[e];
    __syncthreads();
    for (int st = 128; st > 0; st >>= 1) {
        if (tid < st) {
#pragma unroll
            for (int e = 0; e < ENUM; e++) red[e][tid] += red[e][tid + st];
        }
        __syncthreads();
    }
    if (tid == 0) {
        float l[ENUM], mx = -1e30f;
#pragma unroll
        for (int e = 0; e < ENUM; e++) { l[e] = red[e][0]; mx = fmaxf(mx, l[e]); }
        float p[ENUM], sum = 0.f;
#pragma unroll
        for (int e = 0; e < ENUM; e++) { p[e] = expf(l[e] - mx); sum += p[e]; }
#pragma unroll
        for (int e = 0; e < ENUM; e++) p[e] /= sum;
        int i0 = 0;
#pragma unroll
        for (int e = 1; e < ENUM; e++) if (p[e] > p[i0]) i0 = e;
        int i1 = -1;
#pragma unroll
        for (int e = 0; e < ENUM; e++)
            if (e != i0 && (i1 < 0 || p[e] > p[i1])) i1 = e;
        float r0 = p[i0], r1 = p[i1], rs = r0 + r1;
        d_sel[2 * s] = i0;  d_sel[2 * s + 1] = i1;
        d_rw[2 * s] = r0 / rs;  d_rw[2 * s + 1] = r1 / rs;
    }
}

// -------------- dispatch: per-expert ranks, drops, compact mapping ----------
__global__ void dispatch_kernel() {
    int e = threadIdx.x;
    if (e >= ENUM) return;
    int c = 0;
    for (int i = 0; i < SLEN * 2; i++) c += (d_sel[i] == e);
    int drop = c > CAP ? c - CAP : 0;
    d_m[e] = c - drop;
    int r = 0;
    for (int i = 0; i < SLEN * 2; i++) {
        if (d_sel[i] == e) {
            if (r >= drop) {
                int j = r - drop;
                d_tok[e * CAP + j] = i >> 1;
                d_pos[i] = e * CAP + j;
            } else {
                d_pos[i] = -1;
            }
            r++;
        }
    }
}

// -------------- gather valid tokens into compact per-expert buffers ---------
__global__ void gather_kernel(const float* __restrict__ hidden) {
    int row = blockIdx.x;
    int e = row >> 10, t = row & 1023;
    if (t >= d_m[e]) return;
    const float* src = hidden + (size_t)d_tok[row] * DDIM;
    float* dst = d_xg + (size_t)row * DDIM;
    for (int d = threadIdx.x * 4; d < DDIM; d += 256 * 4)
        *(float4*)(dst + d) = *(const float4*)(src + d);
}

// -------------- fp32 GEMM via packed FFMA2: 128x128 tile, 8x8 microtile -----
__global__ __launch_bounds__(256, 2)
void gemm128(const float* __restrict__ A, const float* __restrict__ W,
             float* __restrict__ C, int M, int N, int K,
             long long aStride, long long wStride, long long cStride,
             int useM) {
    int z = blockIdx.z;
    int mlim = useM ? d_m[z] : M;
    int row0 = blockIdx.y * 128;
    if (row0 >= mlim) return;
    A += (size_t)z * aStride; W += (size_t)z * wStride; C += (size_t)z * cStride;
    int col0 = blockIdx.x * 128;

    __shared__ float As[16][128];   // As[k][row] (transposed)
    __shared__ float Bs[16][128];   // Bs[k][col]

    int tid = threadIdx.x;
    // A loader: each thread loads 8 consecutive k of one row
    int arow = tid >> 1;
    int ak   = (tid & 1) * 8;
    // B loader: each thread loads 8 consecutive cols of one k
    int brow = tid >> 4;
    int bcol = (tid & 15) * 8;
    const float* Ap = A + (size_t)(row0 + arow) * K + ak;
    const float* Wp = W + (size_t)brow * N + col0 + bcol;
    bool aval = (row0 + arow) < mlim;

    int tm = tid >> 4;    // rows tm*8 .. +7
    int tn = tid & 15;    // cols tn*8 .. +7

    unsigned long long acc[8][4];
#pragma unroll
    for (int i = 0; i < 8; i++)
#pragma unroll
        for (int j = 0; j < 4; j++) acc[i][j] = 0ULL;

    float4 pa0, pa1, pb0, pb1;
    const float4 z4 = make_float4(0.f, 0.f, 0.f, 0.f);
    pa0 = aval ? *(const float4*)(Ap + 0) : z4;
    pa1 = aval ? *(const float4*)(Ap + 4) : z4;
    pb0 = *(const float4*)(Wp + 0);
    pb1 = *(const float4*)(Wp + 4);

    for (int k0 = 0; k0 < K; k0 += 16) {
        As[ak + 0][arow] = pa0.x; As[ak + 1][arow] = pa0.y;
        As[ak + 2][arow] = pa0.z; As[ak + 3][arow] = pa0.w;
        As[ak + 4][arow] = pa1.x; As[ak + 5][arow] = pa1.y;
        As[ak + 6][arow] = pa1.z; As[ak + 7][arow] = pa1.w;
        *(float4*)&Bs[brow][bcol] = pb0;
        *(float4*)&Bs[brow][bcol + 4] = pb1;
        __syncthreads();

        if (k0 + 16 < K) {
            pa0 = aval ? *(const float4*)(Ap + k0 + 16) : z4;
            pa1 = aval ? *(const float4*)(Ap + k0 + 20) : z4;
            pb0 = *(const float4*)(Wp + (size_t)(k0 + 16) * N);
            pb1 = *(const float4*)(Wp + (size_t)(k0 + 16) * N + 4);
        }

#pragma unroll
        for (int kk = 0; kk < 16; kk++) {
            float4 av0 = *(const float4*)&As[kk][tm * 8];
            float4 av1 = *(const float4*)&As[kk][tm * 8 + 4];
            ulonglong2 bu0 = *(const ulonglong2*)&Bs[kk][tn * 8];
            ulonglong2 bu1 = *(const ulonglong2*)&Bs[kk][tn * 8 + 4];
            float aa[8] = {av0.x, av0.y, av0.z, av0.w, av1.x, av1.y, av1.z, av1.w};
#pragma unroll
            for (int i = 0; i < 8; i++) {
                unsigned long long ap = pk2(aa[i], aa[i]);
                acc[i][0] = fma2(ap, bu0.x, acc[i][0]);
                acc[i][1] = fma2(ap, bu0.y, acc[i][1]);
                acc[i][2] = fma2(ap, bu1.x, acc[i][2]);
                acc[i][3] = fma2(ap, bu1.y, acc[i][3]);
            }
        }
        __syncthreads();
    }

#pragma unroll
    for (int i = 0; i < 8; i++) {
        int r = row0 + tm * 8 + i;
        if (r < mlim) {
            float2 f0 = upk2(acc[i][0]);
            float2 f1 = upk2(acc[i][1]);
            float2 f2 = upk2(acc[i][2]);
            float2 f3 = upk2(acc[i][3]);
            float* Cp = C + (size_t)r * N + col0 + tn * 8;
            *(float4*)(Cp + 0) = make_float4(f0.x, f0.y, f1.x, f1.y);
            *(float4*)(Cp + 4) = make_float4(f2.x, f2.y, f3.x, f3.y);
        }
    }
}

// -------------- beta / g projections (N=6 each): warp per row ----------------
__global__ void bg_kernel(const float* __restrict__ b_w, const float* __restrict__ a_w,
                          const float* __restrict__ A_log, const float* __restrict__ dt_bias) {
    int row = blockIdx.x * 8 + (threadIdx.x >> 5);
    int lane = threadIdx.x & 31;
    int e = row >> 10, t = row & 1023;
    if (t >= d_m[e]) return;
    const float* x = d_xg + (size_t)row * DDIM;
    const float* bw = b_w + (size_t)e * DDIM * HNUM;
    const float* aw = a_w + (size_t)e * DDIM * HNUM;
    float ba[HNUM], aa[HNUM];
#pragma unroll
    for (int h = 0; h < HNUM; h++) { ba[h] = 0.f; aa[h] = 0.f; }
    for (int d = lane; d < DDIM; d += 32) {
        float xv = x[d];
        const float* bp = bw + (size_t)d * HNUM;
        const float* ap = aw + (size_t)d * HNUM;
#pragma unroll
        for (int h = 0; h < HNUM; h++) { ba[h] += xv * bp[h]; aa[h] += xv * ap[h]; }
    }
#pragma unroll
    for (int h = 0; h < HNUM; h++) {
#pragma unroll
        for (int o = 16; o; o >>= 1) {
            ba[h] += __shfl_xor_sync(0xffffffffu, ba[h], o);
            aa[h] += __shfl_xor_sync(0xffffffffu, aa[h], o);
        }
    }
    if (lane == 0) {
#pragma unroll
        for (int h = 0; h < HNUM; h++) {
            d_beta[row * HNUM + h] = 1.f / (1.f + expf(-ba[h]));
            float xx = aa[h] + dt_bias[h];
            float sp = xx > 20.f ? xx : log1pf(expf(xx));
            d_g[row * HNUM + h] = -expf(A_log[h]) * sp;
        }
    }
}

// -------------- depthwise causal conv(4) + silu + per-head l2norm (q,k) -----
__global__ void convnorm_kernel(const float* __restrict__ pre, const float* __restrict__ cw,
                                float* __restrict__ out, float scale) {
    int row = blockIdx.x;
    int h = blockIdx.y;
    int e = row >> 10, t = row & 1023;
    if (t >= d_m[e]) return;
    int tid = threadIdx.x;
    int ch = h * DKC + tid;
    float y = 0.f;
#pragma unroll
    for (int j = 0; j < 4; j++) {
        int tt = t - 3 + j;
        if (tt >= 0) y += cw[ch * 4 + j] * pre[(size_t)(row - 3 + j) * KDIM + ch];
    }
    y = y / (1.f + expf(-y));      // silu
    __shared__ float red[256];
    red[tid] = y * y;
    __syncthreads();
    for (int st = 128; st > 0; st >>= 1) {
        if (tid < st) red[tid] += red[tid + st];
        __syncthreads();
    }
    float inv = rsqrtf(red[0] + 1e-6f) * scale;
    out[(size_t)row * KDIM + ch] = y * inv;
}

// -------------- depthwise causal conv(4) + silu for v ------------------------
__global__ void convv_kernel(const float* __restrict__ pre, const float* __restrict__ cw,
                             float* __restrict__ out) {
    int idx = blockIdx.x * 256 + threadIdx.x;
    int row = idx / VDIM;
    int ch = idx - row * VDIM;
    int e = row >> 10, t = row & 1023;
    if (t >= d_m[e]) return;
    float y = 0.f;
#pragma unroll
    for (int j = 0; j < 4; j++) {
        int tt = t - 3 + j;
        if (tt >= 0) y += cw[ch * 4 + j] * pre[(size_t)(row - 3 + j) * VDIM + ch];
    }
    out[(size_t)row * VDIM + ch] = y / (1.f + expf(-y));
}

// -------------- gated delta-rule recurrence ----------------------------------
// block = (e, h, vchunk of 32). State S[32][256] in smem. Warp-private 4 v-lanes.
// carries u = k_t . S_{t-1}, w = q_t . S_{t-1} computed in previous fused pass.
// All of t+1's operands (k,q,v,beta,g) are prefetched before the state pass.
__global__ void recur_kernel() {
    int vc = blockIdx.x;           // 0..15
    int h = blockIdx.y;            // 0..5
    int e = blockIdx.z;            // 0..7
    int m = d_m[e];
    __shared__ float S[32 * 256];
    __shared__ float su[32], sw[32], sd[32];
    int tid = threadIdx.x, warp = tid >> 5, lane = tid & 31;
    int v0 = warp * 4;
    for (int i = lane; i < 4 * 256; i += 32) S[v0 * 256 + i] = 0.f;
    if (lane < 4) { su[v0 + lane] = 0.f; sw[v0 + lane] = 0.f; }
    __syncwarp();
    if (m == 0) return;

    const float* kb = d_kn + (size_t)(e * CAP) * KDIM + h * DKC;
    const float* qb = d_qn + (size_t)(e * CAP) * KDIM + h * DKC;
    const float* vb = d_vn + (size_t)(e * CAP) * VDIM + h * DVC + vc * 32;
    const float* bb = d_beta + (size_t)(e * CAP) * HNUM + h;
    const float* gb = d_g + (size_t)(e * CAP) * HNUM + h;
    float* ob = d_o + (size_t)(e * CAP) * VDIM + h * DVC + vc * 32;

    float kc[8], qc[8];
#pragma unroll
    for (int j = 0; j < 8; j++) { kc[j] = kb[lane + 32 * j]; qc[j] = qb[lane + 32 * j]; }
    float beta = bb[0];
    float gv = gb[0];
    float vv = (lane < 4) ? vb[v0 + lane] : 0.f;

    for (int t = 0; t < m; t++) {
        float eg = expf(gv);
        float qk = 0.f;
#pragma unroll
        for (int j = 0; j < 8; j++) qk += kc[j] * qc[j];
#pragma unroll
        for (int o = 16; o; o >>= 1) qk += __shfl_xor_sync(0xffffffffu, qk, o);

        if (lane < 4) {
            int v = v0 + lane;
            float dd = beta * (vv - eg * su[v]);
            ob[(size_t)t * VDIM + v] = eg * sw[v] + qk * dd;
            sd[v] = dd;
        }
        __syncwarp();

        // prefetch everything for t+1 so load latency overlaps the state pass
        float kn2[8], qn2[8];
        float beta_n = 0.f, g_n = 0.f, vv_n = 0.f;
        if (t + 1 < m) {
            const float* kr = kb + (size_t)(t + 1) * KDIM;
            const float* qr = qb + (size_t)(t + 1) * KDIM;
#pragma unroll
            for (int j = 0; j < 8; j++) { kn2[j] = kr[lane + 32 * j]; qn2[j] = qr[lane + 32 * j]; }
            beta_n = bb[(size_t)(t + 1) * HNUM];
            g_n = gb[(size_t)(t + 1) * HNUM];
            if (lane < 4) vv_n = vb[(size_t)(t + 1) * VDIM + v0 + lane];
        } else {
#pragma unroll
            for (int j = 0; j < 8; j++) { kn2[j] = 0.f; qn2[j] = 0.f; }
        }

#pragma unroll
        for (int vi = 0; vi < 4; vi++) {
            int v = v0 + vi;
            float dd = sd[v];
            float un = 0.f, wn = 0.f;
            float* Sr = &S[v * 256];
#pragma unroll
            for (int j = 0; j < 8; j++) {
                float s2 = Sr[lane + 32 * j];
                s2 = eg * s2 + kc[j] * dd;
                Sr[lane + 32 * j] = s2;
                un += kn2[j] * s2;
                wn += qn2[j] * s2;
            }
#pragma unroll
            for (int o = 16; o; o >>= 1) {
                un += __shfl_xor_sync(0xffffffffu, un, o);
                wn += __shfl_xor_sync(0xffffffffu, wn, o);
            }
            if (lane == 0) { su[v] = un; sw[v] = wn; }
        }
        __syncwarp();
#pragma unroll
        for (int j = 0; j < 8; j++) { kc[j] = kn2[j]; qc[j] = qn2[j]; }
        beta = beta_n; gv = g_n; vv = vv_n;
    }
}

// -------------- combine (scatter back) + gated RMSNorm -----------------------
__global__ void combine_kernel(const float* __restrict__ norm_w) {
    int s = blockIdx.x, h = blockIdx.y, tid = threadIdx.x;
    int p0 = d_pos[2 * s], p1 = d_pos[2 * s + 1];
    float r0 = d_rw[2 * s], r1 = d_rw[2 * s + 1];
    float acc[2];
    float ss = 0.f;
#pragma unroll
    for (int i = 0; i < 2; i++) {
        int v = tid + i * 256;
        float a = 0.f;
        if (p0 >= 0) a += r0 * d_o[(size_t)p0 * VDIM + h * DVC + v];
        if (p1 >= 0) a += r1 * d_o[(size_t)p1 * VDIM + h * DVC + v];
        acc[i] = a;
        ss += a * a;
    }
    __shared__ float red[256];
    red[tid] = ss;
    __syncthreads();
    for (int st = 128; st > 0; st >>= 1) {
        if (tid < st) red[tid] += red[tid + st];
        __syncthreads();
    }
    float inv = rsqrtf(red[0] / (float)DVC + 1e-5f);
#pragma unroll
    for (int i = 0; i < 2; i++) {
        int v = tid + i * 256;
        float gg = d_gg[(size_t)s * VDIM + h * DVC + v];
        float sg = gg / (1.f + expf(-gg));
        d_pre[(size_t)s * VDIM + h * DVC + v] = acc[i] * inv * norm_w[v] * sg;
    }
}

// ----------------------------- launch ----------------------------------------
extern "C" void kernel_launch(void* const* d_in, const int* in_sizes, int n_in,
                              void* d_out, int out_size) {
    const float* hidden  = (const float*)d_in[0];
    const float* q_w     = (const float*)d_in[1];
    const float* gate_w  = (const float*)d_in[2];
    const float* k_w     = (const float*)d_in[3];
    const float* v_w     = (const float*)d_in[4];
    const float* b_w     = (const float*)d_in[5];
    const float* a_w     = (const float*)d_in[6];
    const float* A_log   = (const float*)d_in[7];
    const float* dt_bias = (const float*)d_in[8];
    const float* qcw     = (const float*)d_in[9];
    const float* kcw     = (const float*)d_in[10];
    const float* vcw     = (const float*)d_in[11];
    const float* g_w     = (const float*)d_in[12];
    const float* norm_w  = (const float*)d_in[13];
    const float* o_w     = (const float*)d_in[14];

    float *xg, *qpre, *kpre, *vpre, *gg, *pre;
    cudaGetSymbolAddress((void**)&xg, d_xg);
    cudaGetSymbolAddress((void**)&qpre, d_qpre);
    cudaGetSymbolAddress((void**)&kpre, d_kpre);
    cudaGetSymbolAddress((void**)&vpre, d_vpre);
    cudaGetSymbolAddress((void**)&gg, d_gg);
    cudaGetSymbolAddress((void**)&pre, d_pre);

    router_kernel<<<SLEN, 256>>>(hidden, gate_w);
    dispatch_kernel<<<1, 32>>>();
    gather_kernel<<<NROW, 256>>>(hidden);

    dim3 gq(KDIM / 128, CAP / 128, ENUM);
    gemm128<<<gq, 256>>>(xg, q_w, qpre, CAP, KDIM, DDIM,
                         (long long)CAP * DDIM, 0LL, (long long)CAP * KDIM, 1);
    gemm128<<<gq, 256>>>(xg, k_w, kpre, CAP, KDIM, DDIM,
                         (long long)CAP * DDIM, (long long)DDIM * KDIM,
                         (long long)CAP * KDIM, 1);
    dim3 gv(VDIM / 128, CAP / 128, ENUM);
    gemm128<<<gv, 256>>>(xg, v_w, vpre, CAP, VDIM, DDIM,
                         (long long)CAP * DDIM, (long long)DDIM * VDIM,
                         (long long)CAP * VDIM, 1);

    bg_kernel<<<NROW / 8, 256>>>(b_w, a_w, A_log, dt_bias);

    float *qn, *kn, *vn;
    cudaGetSymbolAddress((void**)&qn, d_qn);
    cudaGetSymbolAddress((void**)&kn, d_kn);
    cudaGetSymbolAddress((void**)&vn, d_vn);

    dim3 gc(NROW, HNUM);
    convnorm_kernel<<<gc, 256>>>(qpre, qcw, qn, 0.0625f);  // DK^-0.5 = 1/16
    convnorm_kernel<<<gc, 256>>>(kpre, kcw, kn, 1.0f);
    convv_kernel<<<(NROW * (VDIM / 256)), 256>>>(vpre, vcw, vn);

    recur_kernel<<<dim3(DVC / 32, HNUM, ENUM), 256>>>();

    gemm128<<<dim3(VDIM / 128, SLEN / 128, 1), 256>>>(hidden, g_w, gg, SLEN, VDIM, DDIM,
                                                      0LL, 0LL, 0LL, 0);
    combine_kernel<<<dim3(SLEN, HNUM), 256>>>(norm_w);
    gemm128<<<dim3(DDIM / 128, SLEN / 128, 1), 256>>>(pre, o_w, (float*)d_out,
                                                      SLEN, DDIM, VDIM, 0LL, 0LL, 0LL, 0);
}

// round 4
// speedup vs baseline: 1.5796x; 1.5744x over previous
#include <cuda_runtime.h>
#include <cuda_bf16.h>
#include <stdint.h>
#include <math.h>

#define SLEN 1024
#define DDIM 2048
#define ENUM 8
#define HNUM 6
#define DKC  256
#define DVC  512
#define KDIM 1536   // HNUM*DKC
#define VDIM 3072   // HNUM*DVC
#define CAP  1024
#define NROW (ENUM*CAP)

// ---------------- scratch (device globals; no allocation in kernel_launch) ----
__device__ int   d_sel[SLEN*2];
__device__ float d_rw [SLEN*2];
__device__ int   d_m  [ENUM];
__device__ int   d_tok[NROW];
__device__ int   d_pos[SLEN*2];
__device__ float d_xg  [NROW*DDIM];
__device__ float d_qpre[NROW*KDIM];
__device__ float d_kpre[NROW*KDIM];
__device__ float d_vpre[NROW*VDIM];
__device__ float d_qn  [NROW*KDIM];
__device__ float d_kn  [NROW*KDIM];
__device__ float d_vn  [NROW*VDIM];
__device__ float d_beta[NROW*HNUM];
__device__ float d_g   [NROW*HNUM];
__device__ float d_o   [NROW*VDIM];
__device__ float d_gg  [SLEN*VDIM];
__device__ float d_pre [SLEN*VDIM];

// bf16 hi/lo split buffers
__device__ __align__(256) __nv_bfloat16 d_xg_hi[NROW*DDIM];
__device__ __align__(256) __nv_bfloat16 d_xg_lo[NROW*DDIM];
__device__ __align__(256) __nv_bfloat16 d_qw_hi[DDIM*KDIM];
__device__ __align__(256) __nv_bfloat16 d_qw_lo[DDIM*KDIM];
__device__ __align__(256) __nv_bfloat16 d_kw_hi[ENUM*DDIM*KDIM];
__device__ __align__(256) __nv_bfloat16 d_kw_lo[ENUM*DDIM*KDIM];
__device__ __align__(256) __nv_bfloat16 d_vw_hi[ENUM*DDIM*VDIM];
__device__ __align__(256) __nv_bfloat16 d_vw_lo[ENUM*DDIM*VDIM];
__device__ __align__(256) __nv_bfloat16 d_gw_hi[DDIM*VDIM];
__device__ __align__(256) __nv_bfloat16 d_gw_lo[DDIM*VDIM];
__device__ __align__(256) __nv_bfloat16 d_ow_hi[VDIM*DDIM];
__device__ __align__(256) __nv_bfloat16 d_ow_lo[VDIM*DDIM];
__device__ __align__(256) __nv_bfloat16 d_hid_hi[SLEN*DDIM];
__device__ __align__(256) __nv_bfloat16 d_hid_lo[SLEN*DDIM];
__device__ __align__(256) __nv_bfloat16 d_pre_hi[SLEN*VDIM];
__device__ __align__(256) __nv_bfloat16 d_pre_lo[SLEN*VDIM];

// ---------------- PTX helpers -------------------------------------------------
__device__ __forceinline__ void cpa16(uint32_t d, const void* s) {
    asm volatile("cp.async.cg.shared.global [%0], [%1], 16;" :: "r"(d), "l"(s));
}
__device__ __forceinline__ void ldm_x4(uint32_t* r, uint32_t a) {
    asm volatile("ldmatrix.sync.aligned.m8n8.x4.shared.b16 {%0,%1,%2,%3}, [%4];"
                 : "=r"(r[0]), "=r"(r[1]), "=r"(r[2]), "=r"(r[3]) : "r"(a));
}
__device__ __forceinline__ void ldm_x4t(uint32_t* r, uint32_t a) {
    asm volatile("ldmatrix.sync.aligned.m8n8.x4.trans.shared.b16 {%0,%1,%2,%3}, [%4];"
                 : "=r"(r[0]), "=r"(r[1]), "=r"(r[2]), "=r"(r[3]) : "r"(a));
}
__device__ __forceinline__ void mma_bf16(float* c, const uint32_t* a, const uint32_t* b) {
    asm volatile(
        "mma.sync.aligned.m16n8k16.row.col.f32.bf16.bf16.f32 "
        "{%0,%1,%2,%3},{%4,%5,%6,%7},{%8,%9},{%0,%1,%2,%3};"
        : "+f"(c[0]), "+f"(c[1]), "+f"(c[2]), "+f"(c[3])
        : "r"(a[0]), "r"(a[1]), "r"(a[2]), "r"(a[3]), "r"(b[0]), "r"(b[1]));
}

// ---------------- hi/lo split conversion --------------------------------------
__device__ __forceinline__ void split4(float4 v, __nv_bfloat162* hi, __nv_bfloat162* lo) {
    __nv_bfloat16 h0 = __float2bfloat16(v.x), h1 = __float2bfloat16(v.y);
    __nv_bfloat16 h2 = __float2bfloat16(v.z), h3 = __float2bfloat16(v.w);
    __nv_bfloat16 l0 = __float2bfloat16(v.x - __bfloat162float(h0));
    __nv_bfloat16 l1 = __float2bfloat16(v.y - __bfloat162float(h1));
    __nv_bfloat16 l2 = __float2bfloat16(v.z - __bfloat162float(h2));
    __nv_bfloat16 l3 = __float2bfloat16(v.w - __bfloat162float(h3));
    hi[0] = __halves2bfloat162(h0, h1);
    hi[1] = __halves2bfloat162(h2, h3);
    lo[0] = __halves2bfloat162(l0, l1);
    lo[1] = __halves2bfloat162(l2, l3);
}

__global__ void split_kernel(const float4* __restrict__ x, __nv_bfloat162* __restrict__ hi,
                             __nv_bfloat162* __restrict__ lo, int n4) {
    int i = blockIdx.x * 256 + threadIdx.x;
    if (i >= n4) return;
    __nv_bfloat162 h[2], l[2];
    split4(x[i], h, l);
    hi[2 * i] = h[0]; hi[2 * i + 1] = h[1];
    lo[2 * i] = l[0]; lo[2 * i + 1] = l[1];
}

__global__ void split_xg_kernel() {
    int row = blockIdx.x;
    int e = row >> 10, t = row & 1023;
    if (t >= d_m[e]) return;
    const float4* src = (const float4*)(d_xg + (size_t)row * DDIM);
    __nv_bfloat162* hi = (__nv_bfloat162*)(d_xg_hi + (size_t)row * DDIM);
    __nv_bfloat162* lo = (__nv_bfloat162*)(d_xg_lo + (size_t)row * DDIM);
    for (int i = threadIdx.x; i < DDIM / 4; i += 256) {
        __nv_bfloat162 h[2], l[2];
        split4(src[i], h, l);
        hi[2 * i] = h[0]; hi[2 * i + 1] = h[1];
        lo[2 * i] = l[0]; lo[2 * i + 1] = l[1];
    }
}

// ---------------- tensor-core split-bf16 GEMM ---------------------------------
// C = A @ B exact-ish: A=Ahi+Alo, B=Bhi+Blo, C = AhBh + AhBl + AlBh.
// Block tile 128x128, ktile 32, 8 warps of 64x32, cp.async double buffer.
#define LDA 40
#define LDB 136
#define A_SZ (128*LDA)
#define B_SZ (32*LDB)
#define STAGE_H (2*A_SZ + 2*B_SZ)
#define GEMM_SMEM (STAGE_H*2*2)

__global__ __launch_bounds__(256, 2)
void gemm_tc(const __nv_bfloat16* __restrict__ Ahi, const __nv_bfloat16* __restrict__ Alo,
             const __nv_bfloat16* __restrict__ Bhi, const __nv_bfloat16* __restrict__ Blo,
             float* __restrict__ C, int M, int N, int K,
             long long aStride, long long bStride, long long cStride, int useM) {
    extern __shared__ __nv_bfloat16 smbuf[];
    int z = blockIdx.z;
    int mlim = useM ? d_m[z] : M;
    int row0 = blockIdx.y * 128;
    if (row0 >= mlim) return;
    int col0 = blockIdx.x * 128;
    Ahi += (size_t)z * aStride; Alo += (size_t)z * aStride;
    Bhi += (size_t)z * bStride; Blo += (size_t)z * bStride;
    C += (size_t)z * cStride;

    uint32_t sbase = (uint32_t)__cvta_generic_to_shared(smbuf);
    int t = threadIdx.x;

    // loader mapping: A: row t>>1, 16-half chunk (t&1); B: row t>>3, chunk (t&7)
    int arow = t >> 1, akc = (t & 1) * 16;
    int brow = t >> 3, bnc = (t & 7) * 16;
    const __nv_bfloat16* gAh = Ahi + (size_t)(row0 + arow) * K + akc;
    const __nv_bfloat16* gAl = Alo + (size_t)(row0 + arow) * K + akc;
    const __nv_bfloat16* gBh = Bhi + (size_t)brow * N + col0 + bnc;
    const __nv_bfloat16* gBl = Blo + (size_t)brow * N + col0 + bnc;
    uint32_t dAh = sbase + (uint32_t)(arow * LDA + akc) * 2;
    uint32_t dAl = dAh + A_SZ * 2;
    uint32_t dBh = sbase + (uint32_t)(2 * A_SZ + brow * LDB + bnc) * 2;
    uint32_t dBl = dBh + B_SZ * 2;

    int lane = t & 31, wid = t >> 5;
    int wm = (wid >> 2) * 64, wn = (wid & 3) * 32;
    // ldmatrix lane address components
    int aR = lane & 15, aC = (lane >> 4) * 8;
    uint32_t aOff = (uint32_t)((wm + aR) * LDA + aC) * 2;
    int bgp = lane >> 3, blr = lane & 7;
    int bR = blr + (bgp & 1) * 8, bC = (bgp >> 1) * 8;
    uint32_t bOff = (uint32_t)(bR * LDB + wn + bC) * 2;

    float acc[4][4][4];
#pragma unroll
    for (int mi = 0; mi < 4; mi++)
#pragma unroll
        for (int ni = 0; ni < 4; ni++)
#pragma unroll
            for (int j = 0; j < 4; j++) acc[mi][ni][j] = 0.f;

    int KT = K / 32;

    // prologue load (stage 0)
    cpa16(dAh, gAh);           cpa16(dAh + 16, gAh + 8);
    cpa16(dAl, gAl);           cpa16(dAl + 16, gAl + 8);
    cpa16(dBh, gBh);           cpa16(dBh + 16, gBh + 8);
    cpa16(dBl, gBl);           cpa16(dBl + 16, gBl + 8);
    asm volatile("cp.async.commit_group;");

    for (int kt = 0; kt < KT; kt++) {
        if (kt + 1 < KT) {
            int k0 = (kt + 1) * 32;
            uint32_t so = (uint32_t)(((kt + 1) & 1) * STAGE_H) * 2;
            const __nv_bfloat16* a0 = gAh + k0;
            const __nv_bfloat16* a1 = gAl + k0;
            const __nv_bfloat16* b0 = gBh + (size_t)k0 * N;
            const __nv_bfloat16* b1 = gBl + (size_t)k0 * N;
            cpa16(dAh + so, a0);        cpa16(dAh + so + 16, a0 + 8);
            cpa16(dAl + so, a1);        cpa16(dAl + so + 16, a1 + 8);
            cpa16(dBh + so, b0);        cpa16(dBh + so + 16, b0 + 8);
            cpa16(dBl + so, b1);        cpa16(dBl + so + 16, b1 + 8);
            asm volatile("cp.async.commit_group;");
            asm volatile("cp.async.wait_group 1;");
        } else {
            asm volatile("cp.async.wait_group 0;");
        }
        __syncthreads();

        uint32_t s0 = sbase + (uint32_t)((kt & 1) * STAGE_H) * 2;
        uint32_t sAh = s0 + aOff;
        uint32_t sAl = sAh + (uint32_t)A_SZ * 2;
        uint32_t sBh = s0 + (uint32_t)(2 * A_SZ) * 2 + bOff;
        uint32_t sBl = sBh + (uint32_t)B_SZ * 2;

#pragma unroll
        for (int ks = 0; ks < 2; ks++) {
            uint32_t kao = (uint32_t)(ks * 16) * 2;
            uint32_t kbo = (uint32_t)(ks * 16 * LDB) * 2;
            uint32_t bh[8], bl2[8], af[16];
            ldm_x4t(bh + 0, sBh + kbo);
            ldm_x4t(bh + 4, sBh + kbo + 32);
            ldm_x4t(bl2 + 0, sBl + kbo);
            ldm_x4t(bl2 + 4, sBl + kbo + 32);
#pragma unroll
            for (int mi = 0; mi < 4; mi++)
                ldm_x4(af + mi * 4, sAh + kao + (uint32_t)(mi * 16 * LDA) * 2);
#pragma unroll
            for (int mi = 0; mi < 4; mi++)
#pragma unroll
                for (int ni = 0; ni < 4; ni++)
                    mma_bf16(acc[mi][ni], af + mi * 4, bh + (ni >> 1) * 4 + (ni & 1) * 2);
#pragma unroll
            for (int mi = 0; mi < 4; mi++)
#pragma unroll
                for (int ni = 0; ni < 4; ni++)
                    mma_bf16(acc[mi][ni], af + mi * 4, bl2 + (ni >> 1) * 4 + (ni & 1) * 2);
#pragma unroll
            for (int mi = 0; mi < 4; mi++)
                ldm_x4(af + mi * 4, sAl + kao + (uint32_t)(mi * 16 * LDA) * 2);
#pragma unroll
            for (int mi = 0; mi < 4; mi++)
#pragma unroll
                for (int ni = 0; ni < 4; ni++)
                    mma_bf16(acc[mi][ni], af + mi * 4, bh + (ni >> 1) * 4 + (ni & 1) * 2);
        }
        __syncthreads();
    }

    // epilogue
    int gr = lane >> 2, gc = (lane & 3) * 2;
#pragma unroll
    for (int mi = 0; mi < 4; mi++) {
        int r = row0 + wm + mi * 16 + gr;
#pragma unroll
        for (int ni = 0; ni < 4; ni++) {
            float* Cp = C + (size_t)r * N + col0 + wn + ni * 8 + gc;
            if (r < mlim) {
                Cp[0] = acc[mi][ni][0];
                Cp[1] = acc[mi][ni][1];
            }
            if (r + 8 < mlim) {
                float* Cq = Cp + (size_t)8 * N;
                Cq[0] = acc[mi][ni][2];
                Cq[1] = acc[mi][ni][3];
            }
        }
    }
}

// ---------------- router: logits -> softmax -> top2 -> renorm ---------------
__global__ void router_kernel(const float* __restrict__ hidden,
                              const float* __restrict__ gate_w) {
    int s = blockIdx.x;
    int tid = threadIdx.x;
    float acc[ENUM];
#pragma unroll
    for (int e = 0; e < ENUM; e++) acc[e] = 0.f;
    const float* xr = hidden + (size_t)s * DDIM;
    for (int d = tid; d < DDIM; d += 256) {
        float x = xr[d];
        const float* w = gate_w + (size_t)d * ENUM;
#pragma unroll
        for (int e = 0; e < ENUM; e++) acc[e] += x * w[e];
    }
    __shared__ float red[ENUM][256];
#pragma unroll
    for (int e = 0; e < ENUM; e++) red[e][tid] = acc[e];
    __syncthreads();
    for (int st = 128; st > 0; st >>= 1) {
        if (tid < st) {
#pragma unroll
            for (int e = 0; e < ENUM; e++) red[e][tid] += red[e][tid + st];
        }
        __syncthreads();
    }
    if (tid == 0) {
        float l[ENUM], mx = -1e30f;
#pragma unroll
        for (int e = 0; e < ENUM; e++) { l[e] = red[e][0]; mx = fmaxf(mx, l[e]); }
        float p[ENUM], sum = 0.f;
#pragma unroll
        for (int e = 0; e < ENUM; e++) { p[e] = expf(l[e] - mx); sum += p[e]; }
#pragma unroll
        for (int e = 0; e < ENUM; e++) p[e] /= sum;
        int i0 = 0;
#pragma unroll
        for (int e = 1; e < ENUM; e++) if (p[e] > p[i0]) i0 = e;
        int i1 = -1;
#pragma unroll
        for (int e = 0; e < ENUM; e++)
            if (e != i0 && (i1 < 0 || p[e] > p[i1])) i1 = e;
        float r0 = p[i0], r1 = p[i1], rs = r0 + r1;
        d_sel[2 * s] = i0;  d_sel[2 * s + 1] = i1;
        d_rw[2 * s] = r0 / rs;  d_rw[2 * s + 1] = r1 / rs;
    }
}

// -------------- dispatch: per-expert ranks, drops, compact mapping ----------
__global__ void dispatch_kernel() {
    int e = threadIdx.x;
    if (e >= ENUM) return;
    int c = 0;
    for (int i = 0; i < SLEN * 2; i++) c += (d_sel[i] == e);
    int drop = c > CAP ? c - CAP : 0;
    d_m[e] = c - drop;
    int r = 0;
    for (int i = 0; i < SLEN * 2; i++) {
        if (d_sel[i] == e) {
            if (r >= drop) {
                int j = r - drop;
                d_tok[e * CAP + j] = i >> 1;
                d_pos[i] = e * CAP + j;
            } else {
                d_pos[i] = -1;
            }
            r++;
        }
    }
}

// -------------- gather valid tokens into compact per-expert buffers ---------
__global__ void gather_kernel(const float* __restrict__ hidden) {
    int row = blockIdx.x;
    int e = row >> 10, t = row & 1023;
    if (t >= d_m[e]) return;
    const float* src = hidden + (size_t)d_tok[row] * DDIM;
    float* dst = d_xg + (size_t)row * DDIM;
    for (int d = threadIdx.x * 4; d < DDIM; d += 256 * 4)
        *(float4*)(dst + d) = *(const float4*)(src + d);
}

// -------------- beta / g projections (N=6 each): warp per row ----------------
__global__ void bg_kernel(const float* __restrict__ b_w, const float* __restrict__ a_w,
                          const float* __restrict__ A_log, const float* __restrict__ dt_bias) {
    int row = blockIdx.x * 8 + (threadIdx.x >> 5);
    int lane = threadIdx.x & 31;
    int e = row >> 10, t = row & 1023;
    if (t >= d_m[e]) return;
    const float* x = d_xg + (size_t)row * DDIM;
    const float* bw = b_w + (size_t)e * DDIM * HNUM;
    const float* aw = a_w + (size_t)e * DDIM * HNUM;
    float ba[HNUM], aa[HNUM];
#pragma unroll
    for (int h = 0; h < HNUM; h++) { ba[h] = 0.f; aa[h] = 0.f; }
    for (int d = lane; d < DDIM; d += 32) {
        float xv = x[d];
        const float* bp = bw + (size_t)d * HNUM;
        const float* ap = aw + (size_t)d * HNUM;
#pragma unroll
        for (int h = 0; h < HNUM; h++) { ba[h] += xv * bp[h]; aa[h] += xv * ap[h]; }
    }
#pragma unroll
    for (int h = 0; h < HNUM; h++) {
#pragma unroll
        for (int o = 16; o; o >>= 1) {
            ba[h] += __shfl_xor_sync(0xffffffffu, ba[h], o);
            aa[h] += __shfl_xor_sync(0xffffffffu, aa[h], o);
        }
    }
    if (lane == 0) {
#pragma unroll
        for (int h = 0; h < HNUM; h++) {
            d_beta[row * HNUM + h] = 1.f / (1.f + expf(-ba[h]));
            float xx = aa[h] + dt_bias[h];
            float sp = xx > 20.f ? xx : log1pf(expf(xx));
            d_g[row * HNUM + h] = -expf(A_log[h]) * sp;
        }
    }
}

// -------------- depthwise causal conv(4) + silu + per-head l2norm (q,k) -----
__global__ void convnorm_kernel(const float* __restrict__ pre, const float* __restrict__ cw,
                                float* __restrict__ out, float scale) {
    int row = blockIdx.x;
    int h = blockIdx.y;
    int e = row >> 10, t = row & 1023;
    if (t >= d_m[e]) return;
    int tid = threadIdx.x;
    int ch = h * DKC + tid;
    float y = 0.f;
#pragma unroll
    for (int j = 0; j < 4; j++) {
        int tt = t - 3 + j;
        if (tt >= 0) y += cw[ch * 4 + j] * pre[(size_t)(row - 3 + j) * KDIM + ch];
    }
    y = y / (1.f + expf(-y));      // silu
    __shared__ float red[256];
    red[tid] = y * y;
    __syncthreads();
    for (int st = 128; st > 0; st >>= 1) {
        if (tid < st) red[tid] += red[tid + st];
        __syncthreads();
    }
    float inv = rsqrtf(red[0] + 1e-6f) * scale;
    out[(size_t)row * KDIM + ch] = y * inv;
}

// -------------- depthwise causal conv(4) + silu for v ------------------------
__global__ void convv_kernel(const float* __restrict__ pre, const float* __restrict__ cw,
                             float* __restrict__ out) {
    int idx = blockIdx.x * 256 + threadIdx.x;
    int row = idx / VDIM;
    int ch = idx - row * VDIM;
    int e = row >> 10, t = row & 1023;
    if (t >= d_m[e]) return;
    float y = 0.f;
#pragma unroll
    for (int j = 0; j < 4; j++) {
        int tt = t - 3 + j;
        if (tt >= 0) y += cw[ch * 4 + j] * pre[(size_t)(row - 3 + j) * VDIM + ch];
    }
    out[(size_t)row * VDIM + ch] = y / (1.f + expf(-y));
}

// -------------- gated delta-rule recurrence ----------------------------------
__global__ void recur_kernel() {
    int vc = blockIdx.x;           // 0..15
    int h = blockIdx.y;            // 0..5
    int e = blockIdx.z;            // 0..7
    int m = d_m[e];
    __shared__ float S[32 * 256];
    __shared__ float su[32], sw[32], sd[32];
    int tid = threadIdx.x, warp = tid >> 5, lane = tid & 31;
    int v0 = warp * 4;
    for (int i = lane; i < 4 * 256; i += 32) S[v0 * 256 + i] = 0.f;
    if (lane < 4) { su[v0 + lane] = 0.f; sw[v0 + lane] = 0.f; }
    __syncwarp();
    if (m == 0) return;

    const float* kb = d_kn + (size_t)(e * CAP) * KDIM + h * DKC;
    const float* qb = d_qn + (size_t)(e * CAP) * KDIM + h * DKC;
    const float* vb = d_vn + (size_t)(e * CAP) * VDIM + h * DVC + vc * 32;
    const float* bb = d_beta + (size_t)(e * CAP) * HNUM + h;
    const float* gb = d_g + (size_t)(e * CAP) * HNUM + h;
    float* ob = d_o + (size_t)(e * CAP) * VDIM + h * DVC + vc * 32;

    float kc[8], qc[8];
#pragma unroll
    for (int j = 0; j < 8; j++) { kc[j] = kb[lane + 32 * j]; qc[j] = qb[lane + 32 * j]; }
    float beta = bb[0];
    float gv = gb[0];
    float vv = (lane < 4) ? vb[v0 + lane] : 0.f;

    for (int t = 0; t < m; t++) {
        float eg = expf(gv);
        float qk = 0.f;
#pragma unroll
        for (int j = 0; j < 8; j++) qk += kc[j] * qc[j];
#pragma unroll
        for (int o = 16; o; o >>= 1) qk += __shfl_xor_sync(0xffffffffu, qk, o);

        if (lane < 4) {
            int v = v0 + lane;
            float dd = beta * (vv - eg * su[v]);
            ob[(size_t)t * VDIM + v] = eg * sw[v] + qk * dd;
            sd[v] = dd;
        }
        __syncwarp();

        float kn2[8], qn2[8];
        float beta_n = 0.f, g_n = 0.f, vv_n = 0.f;
        if (t + 1 < m) {
            const float* kr = kb + (size_t)(t + 1) * KDIM;
            const float* qr = qb + (size_t)(t + 1) * KDIM;
#pragma unroll
            for (int j = 0; j < 8; j++) { kn2[j] = kr[lane + 32 * j]; qn2[j] = qr[lane + 32 * j]; }
            beta_n = bb[(size_t)(t + 1) * HNUM];
            g_n = gb[(size_t)(t + 1) * HNUM];
            if (lane < 4) vv_n = vb[(size_t)(t + 1) * VDIM + v0 + lane];
        } else {
#pragma unroll
            for (int j = 0; j < 8; j++) { kn2[j] = 0.f; qn2[j] = 0.f; }
        }

#pragma unroll
        for (int vi = 0; vi < 4; vi++) {
            int v = v0 + vi;
            float dd = sd[v];
            float un = 0.f, wn = 0.f;
            float* Sr = &S[v * 256];
#pragma unroll
            for (int j = 0; j < 8; j++) {
                float s2 = Sr[lane + 32 * j];
                s2 = eg * s2 + kc[j] * dd;
                Sr[lane + 32 * j] = s2;
                un += kn2[j] * s2;
                wn += qn2[j] * s2;
            }
#pragma unroll
            for (int o = 16; o; o >>= 1) {
                un += __shfl_xor_sync(0xffffffffu, un, o);
                wn += __shfl_xor_sync(0xffffffffu, wn, o);
            }
            if (lane == 0) { su[v] = un; sw[v] = wn; }
        }
        __syncwarp();
#pragma unroll
        for (int j = 0; j < 8; j++) { kc[j] = kn2[j]; qc[j] = qn2[j]; }
        beta = beta_n; gv = g_n; vv = vv_n;
    }
}

// -------------- combine (scatter back) + gated RMSNorm -----------------------
__global__ void combine_kernel(const float* __restrict__ norm_w) {
    int s = blockIdx.x, h = blockIdx.y, tid = threadIdx.x;
    int p0 = d_pos[2 * s], p1 = d_pos[2 * s + 1];
    float r0 = d_rw[2 * s], r1 = d_rw[2 * s + 1];
    float acc[2];
    float ss = 0.f;
#pragma unroll
    for (int i = 0; i < 2; i++) {
        int v = tid + i * 256;
        float a = 0.f;
        if (p0 >= 0) a += r0 * d_o[(size_t)p0 * VDIM + h * DVC + v];
        if (p1 >= 0) a += r1 * d_o[(size_t)p1 * VDIM + h * DVC + v];
        acc[i] = a;
        ss += a * a;
    }
    __shared__ float red[256];
    red[tid] = ss;
    __syncthreads();
    for (int st = 128; st > 0; st >>= 1) {
        if (tid < st) red[tid] += red[tid + st];
        __syncthreads();
    }
    float inv = rsqrtf(red[0] / (float)DVC + 1e-5f);
#pragma unroll
    for (int i = 0; i < 2; i++) {
        int v = tid + i * 256;
        float gg = d_gg[(size_t)s * VDIM + h * DVC + v];
        float sg = gg / (1.f + expf(-gg));
        d_pre[(size_t)s * VDIM + h * DVC + v] = acc[i] * inv * norm_w[v] * sg;
    }
}

// ----------------------------- host helpers ----------------------------------
static void launch_split(const float* src, __nv_bfloat16* hi, __nv_bfloat16* lo,
                         long long n) {
    int n4 = (int)(n / 4);
    split_kernel<<<(n4 + 255) / 256, 256>>>((const float4*)src,
                                            (__nv_bfloat162*)hi, (__nv_bfloat162*)lo, n4);
}

// ----------------------------- launch ----------------------------------------
extern "C" void kernel_launch(void* const* d_in, const int* in_sizes, int n_in,
                              void* d_out, int out_size) {
    const float* hidden  = (const float*)d_in[0];
    const float* q_w     = (const float*)d_in[1];
    const float* gate_w  = (const float*)d_in[2];
    const float* k_w     = (const float*)d_in[3];
    const float* v_w     = (const float*)d_in[4];
    const float* b_w     = (const float*)d_in[5];
    const float* a_w     = (const float*)d_in[6];
    const float* A_log   = (const float*)d_in[7];
    const float* dt_bias = (const float*)d_in[8];
    const float* qcw     = (const float*)d_in[9];
    const float* kcw     = (const float*)d_in[10];
    const float* vcw     = (const float*)d_in[11];
    const float* g_w     = (const float*)d_in[12];
    const float* norm_w  = (const float*)d_in[13];
    const float* o_w     = (const float*)d_in[14];

    float* qpre = 0; float* kpre = 0; float* vpre = 0; float* gg = 0; float* pre = 0;
    cudaGetSymbolAddress((void**)&qpre, d_qpre);
    cudaGetSymbolAddress((void**)&kpre, d_kpre);
    cudaGetSymbolAddress((void**)&vpre, d_vpre);
    cudaGetSymbolAddress((void**)&gg, d_gg);
    cudaGetSymbolAddress((void**)&pre, d_pre);
    float* qn = 0; float* kn = 0; float* vn = 0;
    cudaGetSymbolAddress((void**)&qn, d_qn);
    cudaGetSymbolAddress((void**)&kn, d_kn);
    cudaGetSymbolAddress((void**)&vn, d_vn);

    __nv_bfloat16* xgh = 0; __nv_bfloat16* xgl = 0;
    __nv_bfloat16* qwh = 0; __nv_bfloat16* qwl = 0;
    __nv_bfloat16* kwh = 0; __nv_bfloat16* kwl = 0;
    __nv_bfloat16* vwh = 0; __nv_bfloat16* vwl = 0;
    __nv_bfloat16* gwh = 0; __nv_bfloat16* gwl = 0;
    __nv_bfloat16* owh = 0; __nv_bfloat16* owl = 0;
    __nv_bfloat16* hih = 0; __nv_bfloat16* hil = 0;
    __nv_bfloat16* prh = 0; __nv_bfloat16* prl = 0;
    cudaGetSymbolAddress((void**)&xgh, d_xg_hi);
    cudaGetSymbolAddress((void**)&xgl, d_xg_lo);
    cudaGetSymbolAddress((void**)&qwh, d_qw_hi);
    cudaGetSymbolAddress((void**)&qwl, d_qw_lo);
    cudaGetSymbolAddress((void**)&kwh, d_kw_hi);
    cudaGetSymbolAddress((void**)&kwl, d_kw_lo);
    cudaGetSymbolAddress((void**)&vwh, d_vw_hi);
    cudaGetSymbolAddress((void**)&vwl, d_vw_lo);
    cudaGetSymbolAddress((void**)&gwh, d_gw_hi);
    cudaGetSymbolAddress((void**)&gwl, d_gw_lo);
    cudaGetSymbolAddress((void**)&owh, d_ow_hi);
    cudaGetSymbolAddress((void**)&owl, d_ow_lo);
    cudaGetSymbolAddress((void**)&hih, d_hid_hi);
    cudaGetSymbolAddress((void**)&hil, d_hid_lo);
    cudaGetSymbolAddress((void**)&prh, d_pre_hi);
    cudaGetSymbolAddress((void**)&prl, d_pre_lo);

    cudaFuncSetAttribute(gemm_tc, cudaFuncAttributeMaxDynamicSharedMemorySize, GEMM_SMEM);

    router_kernel<<<SLEN, 256>>>(hidden, gate_w);
    dispatch_kernel<<<1, 32>>>();
    gather_kernel<<<NROW, 256>>>(hidden);

    // hi/lo conversions
    split_xg_kernel<<<NROW, 256>>>();
    launch_split(q_w, qwh, qwl, (long long)DDIM * KDIM);
    launch_split(k_w, kwh, kwl, (long long)ENUM * DDIM * KDIM);
    launch_split(v_w, vwh, vwl, (long long)ENUM * DDIM * VDIM);
    launch_split(g_w, gwh, gwl, (long long)DDIM * VDIM);
    launch_split(o_w, owh, owl, (long long)VDIM * DDIM);
    launch_split(hidden, hih, hil, (long long)SLEN * DDIM);

    // per-expert projections on tensor cores
    gemm_tc<<<dim3(KDIM / 128, CAP / 128, ENUM), 256, GEMM_SMEM>>>(
        xgh, xgl, qwh, qwl, qpre, CAP, KDIM, DDIM,
        (long long)CAP * DDIM, 0LL, (long long)CAP * KDIM, 1);
    gemm_tc<<<dim3(KDIM / 128, CAP / 128, ENUM), 256, GEMM_SMEM>>>(
        xgh, xgl, kwh, kwl, kpre, CAP, KDIM, DDIM,
        (long long)CAP * DDIM, (long long)DDIM * KDIM, (long long)CAP * KDIM, 1);
    gemm_tc<<<dim3(VDIM / 128, CAP / 128, ENUM), 256, GEMM_SMEM>>>(
        xgh, xgl, vwh, vwl, vpre, CAP, VDIM, DDIM,
        (long long)CAP * DDIM, (long long)DDIM * VDIM, (long long)CAP * VDIM, 1);
    // gate projection
    gemm_tc<<<dim3(VDIM / 128, SLEN / 128, 1), 256, GEMM_SMEM>>>(
        hih, hil, gwh, gwl, gg, SLEN, VDIM, DDIM, 0LL, 0LL, 0LL, 0);

    bg_kernel<<<NROW / 8, 256>>>(b_w, a_w, A_log, dt_bias);

    dim3 gc(NROW, HNUM);
    convnorm_kernel<<<gc, 256>>>(qpre, qcw, qn, 0.0625f);  // DK^-0.5 = 1/16
    convnorm_kernel<<<gc, 256>>>(kpre, kcw, kn, 1.0f);
    convv_kernel<<<(NROW * (VDIM / 256)), 256>>>(vpre, vcw, vn);

    recur_kernel<<<dim3(DVC / 32, HNUM, ENUM), 256>>>();

    combine_kernel<<<dim3(SLEN, HNUM), 256>>>(norm_w);
    launch_split(pre, prh, prl, (long long)SLEN * VDIM);
    gemm_tc<<<dim3(DDIM / 128, SLEN / 128, 1), 256, GEMM_SMEM>>>(
        prh, prl, owh, owl, (float*)d_out, SLEN, DDIM, VDIM, 0LL, 0LL, 0LL, 0);
}